// round 14
// baseline (speedup 1.0000x reference)
#include <cuda_runtime.h>
#include <cuda_bf16.h>
#include <cstdint>

#define EE    256
#define HH    4
#define DH    64
#define BB    8
#define CC    32
#define RR    255
#define SS    256
#define HID   1024
#define NBC   (BB*CC)
#define LN_EPS 1e-5f

// ---------------- device scratch ----------------
__device__ __align__(16) float g_u[HH*EE];
__device__ __align__(16) float g_cb[HH];
__device__ __align__(16) float g_bias2[EE];
__device__ __align__(16) float g_M2T[HID*EE];      // [j][f]
__device__ __align__(16) float g_W1T[EE*HID];      // [e][j]
__device__ __align__(16) float g_W2T[HID*EE];      // [j][f]
__device__ __align__(16) float g_xbar[NBC*HID];
__device__ __align__(16) float g_mha[NBC*EE];
__device__ __align__(16) float g_ln[NBC*EE];
__device__ __align__(16) float g_hid[NBC*HID];

// ---------------- host-side side stream (created once, outside capture) ----------------
struct SideStream {
    cudaStream_t s;
    cudaEvent_t fork, join;
    SideStream() {
        cudaStreamCreateWithFlags(&s, cudaStreamNonBlocking);
        cudaEventCreateWithFlags(&fork, cudaEventDisableTiming);
        cudaEventCreateWithFlags(&join, cudaEventDisableTiming);
    }
};
static SideStream g_ss;

// ---------------- cp.async helpers ----------------
__device__ __forceinline__ void cp_async16(float* sdst, const float4* gsrc) {
    unsigned sa = (unsigned)__cvta_generic_to_shared(sdst);
    asm volatile("cp.async.ca.shared.global [%0], [%1], 16;" :: "r"(sa), "l"(gsrc));
}
__device__ __forceinline__ void cp_commit() { asm volatile("cp.async.commit_group;"); }
#define CPWAIT(n) asm volatile("cp.async.wait_group " #n ";")

// 4-token FMA: a[t] (float4 over 4 outputs) += m * tv.{component t}
#define ACC4(m, tv) do { \
    a[0].x += (m).x*(tv).x; a[0].y += (m).y*(tv).x; a[0].z += (m).z*(tv).x; a[0].w += (m).w*(tv).x; \
    a[1].x += (m).x*(tv).y; a[1].y += (m).y*(tv).y; a[1].z += (m).z*(tv).y; a[1].w += (m).w*(tv).y; \
    a[2].x += (m).x*(tv).z; a[2].y += (m).y*(tv).z; a[2].z += (m).z*(tv).z; a[2].w += (m).w*(tv).z; \
    a[3].x += (m).x*(tv).w; a[3].y += (m).y*(tv).w; a[3].z += (m).z*(tv).w; a[3].w += (m).w*(tv).w; \
} while(0)

__device__ __forceinline__ float warp_dot256(const float* __restrict__ row,
                                             const float* __restrict__ svec, int lane) {
    float4 w0 = *(const float4*)(row + lane*4);
    float4 w1 = *(const float4*)(row + 128 + lane*4);
    float4 c0 = *(const float4*)(svec + lane*4);
    float4 c1 = *(const float4*)(svec + 128 + lane*4);
    float acc = w0.x*c0.x + w0.y*c0.y + w0.z*c0.z + w0.w*c0.w
              + w1.x*c1.x + w1.y*c1.y + w1.z*c1.z + w1.w*c1.w;
    #pragma unroll
    for (int o = 16; o; o >>= 1) acc += __shfl_xor_sync(0xffffffffu, acc, o);
    return acc;
}

// ---------------- kernel: setupA — u + cb (attn's only deps) ----------------
__global__ __launch_bounds__(256) void setupA_kernel(const float* __restrict__ cls,
                               const float* __restrict__ w_qkv,
                               const float* __restrict__ b_qkv) {
    int bi = blockIdx.x;
    int tid = threadIdx.x;
    if (bi < 8) {
        __shared__ float s_cls[EE];
        __shared__ float s_q[DH];
        __shared__ float s_p[2][128];
        int h = bi >> 1, e0 = (bi & 1) * 128;
        int warp = tid >> 5, lane = tid & 31;
        if (tid < EE) s_cls[tid] = cls[tid];
        __syncthreads();
        #pragma unroll
        for (int r = 0; r < 8; r++) {
            int d = warp*8 + r;
            float acc = warp_dot256(w_qkv + (size_t)(h*DH + d) * EE, s_cls, lane);
            if (lane == 0) s_q[d] = acc + b_qkv[h*DH + d];
        }
        __syncthreads();
        int dg = tid >> 7, e = e0 + (tid & 127);
        float acc = 0.f;
        #pragma unroll 8
        for (int i = 0; i < 32; i++) {
            int d = dg*32 + i;
            acc += s_q[d] * w_qkv[(size_t)(EE + h*DH + d) * EE + e];
        }
        s_p[dg][tid & 127] = acc;
        __syncthreads();
        if (tid < 128)
            g_u[h*EE + e0 + tid] = 0.125f * (s_p[0][tid] + s_p[1][tid]);
        return;
    }
    {
        __shared__ float s_cls[EE];
        __shared__ float s_q0[EE];
        __shared__ float s_w[8];
        int warp = tid >> 5, lane = tid & 31;
        if (tid < EE) s_cls[tid] = cls[tid];
        __syncthreads();
        for (int r = 0; r < 32; r++) {
            int row = warp*32 + r;
            float acc = warp_dot256(w_qkv + (size_t)row * EE, s_cls, lane);
            if (lane == 0) s_q0[row] = acc + b_qkv[row];
        }
        __syncthreads();
        float v = s_q0[tid] * b_qkv[EE + tid];
        #pragma unroll
        for (int o = 16; o; o >>= 1) v += __shfl_xor_sync(0xffffffffu, v, o);
        if ((tid & 31) == 0) s_w[tid >> 5] = v;
        __syncthreads();
        if (tid < HH) g_cb[tid] = 0.125f * (s_w[2*tid] + s_w[2*tid + 1]);
    }
}

// ---------------- kernel: setupB — M2T + transposes + bias2 (side stream) ----------------
__global__ __launch_bounds__(256) void setupB_kernel(const float* __restrict__ w_qkv,
                               const float* __restrict__ b_qkv,
                               const float* __restrict__ w_out,
                               const float* __restrict__ b_out,
                               const float* __restrict__ w1,
                               const float* __restrict__ w2) {
    int bi = blockIdx.x;
    int tid = threadIdx.x;

    if (bi < 64) {
        __shared__ float sa[64][64];
        __shared__ float sb[64][65];
        int h = bi >> 4, e0 = ((bi >> 2) & 3) * 64, f0 = (bi & 3) * 64;
        for (int i = tid; i < 4096; i += 256) {
            int d = i >> 6, el = i & 63;
            sa[d][el] = w_qkv[(size_t)(2*EE + h*64 + d) * EE + e0 + el];
        }
        for (int i = tid; i < 4096; i += 256) {
            int fl = i >> 6, d = i & 63;
            sb[fl][d] = w_out[(size_t)(f0 + fl) * EE + h*64 + d];
        }
        __syncthreads();
        int tx = tid & 15, ty = tid >> 4;
        float acc[4][4] = {};
        #pragma unroll 4
        for (int d = 0; d < 64; d++) {
            float av[4], bv[4];
            #pragma unroll
            for (int i = 0; i < 4; i++) av[i] = sa[d][ty*4 + i];
            #pragma unroll
            for (int i = 0; i < 4; i++) bv[i] = sb[tx*4 + i][d];
            #pragma unroll
            for (int i = 0; i < 4; i++)
                #pragma unroll
                for (int j = 0; j < 4; j++) acc[i][j] += av[i] * bv[j];
        }
        #pragma unroll
        for (int i = 0; i < 4; i++)
            *(float4*)&g_M2T[(size_t)(h*256 + e0 + ty*4 + i) * EE + f0 + tx*4] = *(float4*)acc[i];
        return;
    }
    if (bi < 576) {
        __shared__ float s[32][33];
        int a = bi - 64;
        const float* src; float* dst; int rows, cols, bx, by;
        if (a < 256) {
            src = w1; dst = g_W1T; rows = HID; cols = EE;
            bx = (a & 7) * 32; by = (a >> 3) * 32;
        } else {
            a -= 256;
            src = w2; dst = g_W2T; rows = EE; cols = HID;
            bx = (a & 31) * 32; by = (a >> 5) * 32;
        }
        int tx = tid & 31, ty = tid >> 5;
        #pragma unroll
        for (int r = 0; r < 4; r++)
            s[ty + r*8][tx] = src[(size_t)(by + ty + r*8) * cols + bx + tx];
        __syncthreads();
        #pragma unroll
        for (int r = 0; r < 4; r++)
            dst[(size_t)(bx + ty + r*8) * rows + by + tx] = s[tx][ty + r*8];
        return;
    }
    {
        __shared__ float s_bv[EE];
        int base = (bi - 576) * 32;
        int warp = tid >> 5, lane = tid & 31;
        if (tid < EE) s_bv[tid] = b_qkv[2*EE + tid];
        __syncthreads();
        #pragma unroll
        for (int q = 0; q < 4; q++) {
            int f = base + warp * 4 + q;
            float acc = warp_dot256(w_out + (size_t)f * EE, s_bv, lane);
            if (lane == 0) g_bias2[f] = acc + b_out[f];
        }
    }
}

// ---------------- kernel: attention -> xbar (verified R7-R12) ----------------
__global__ __launch_bounds__(1024) void attn_kernel(const float* __restrict__ x,
                            const int* __restrict__ real_rows,
                            const float* __restrict__ cls) {
    __shared__ __align__(16) float s_u[HH*EE];
    __shared__ __align__(16) float s_sc[HH][SS];
    __shared__ __align__(16) float s_cls[EE];
    __shared__ __align__(16) float s_part[8][HH][EE];
    __shared__ float s_cb[HH];

    int bc  = blockIdx.x;
    int b   = bc >> 5;
    int tid = threadIdx.x;
    int warp = tid >> 5, lane = tid & 31;

    s_u[tid] = g_u[tid];
    if (tid < EE) s_cls[tid] = cls[tid];
    if (tid < HH) s_cb[tid] = g_cb[tid];
    __syncthreads();

    int nk = real_rows[b] + 1;
    const float* xbase = x + (size_t)bc * RR * EE;

    {
        int pos = warp;
        bool have = pos < nk;
        float4 v0, v1;
        if (have) {
            const float* row = (pos == 0) ? s_cls : (xbase + (size_t)(pos - 1) * EE);
            v0 = *(const float4*)(row + lane*4);
            v1 = *(const float4*)(row + 128 + lane*4);
        }
        while (have) {
            int npos = pos + 32;
            bool nh = npos < nk;
            float4 n0, n1;
            if (nh) {
                const float* nrow = xbase + (size_t)(npos - 1) * EE;
                n0 = *(const float4*)(nrow + lane*4);
                n1 = *(const float4*)(nrow + 128 + lane*4);
            }
            float acc[HH];
            #pragma unroll
            for (int h = 0; h < HH; h++) {
                float4 u0 = *(const float4*)(s_u + h*EE + lane*4);
                float4 u1 = *(const float4*)(s_u + h*EE + 128 + lane*4);
                acc[h] = v0.x*u0.x + v0.y*u0.y + v0.z*u0.z + v0.w*u0.w
                       + v1.x*u1.x + v1.y*u1.y + v1.z*u1.z + v1.w*u1.w;
            }
            #pragma unroll
            for (int o = 16; o; o >>= 1) {
                #pragma unroll
                for (int h = 0; h < HH; h++)
                    acc[h] += __shfl_xor_sync(0xffffffffu, acc[h], o);
            }
            if (lane == 0) {
                #pragma unroll
                for (int h = 0; h < HH; h++) s_sc[h][pos] = acc[h] + s_cb[h];
            }
            pos = npos; have = nh; v0 = n0; v1 = n1;
        }
    }
    __syncthreads();

    if (warp < HH) {
        int h = warp;
        float m = -3.0e38f;
        for (int p = lane; p < nk; p += 32) m = fmaxf(m, s_sc[h][p]);
        #pragma unroll
        for (int o = 16; o; o >>= 1) m = fmaxf(m, __shfl_xor_sync(0xffffffffu, m, o));
        float sum = 0.f;
        for (int p = lane; p < nk; p += 32) {
            float ev = __expf(s_sc[h][p] - m);
            s_sc[h][p] = ev;
            sum += ev;
        }
        #pragma unroll
        for (int o = 16; o; o >>= 1) sum += __shfl_xor_sync(0xffffffffu, sum, o);
        float inv = 1.f / sum;
        for (int p = lane; p < nk; p += 32) s_sc[h][p] *= inv;
    }
    __syncthreads();

    int pg = tid >> 7, ec = tid & 127;
    float2 a[HH];
    #pragma unroll
    for (int h = 0; h < HH; h++) a[h] = make_float2(0.f, 0.f);
    #pragma unroll 8
    for (int pos = pg; pos < nk; pos += 8) {
        float2 xv = (pos == 0) ? *(const float2*)(s_cls + ec*2)
                               : *(const float2*)(xbase + (size_t)(pos - 1) * EE + ec*2);
        #pragma unroll
        for (int h = 0; h < HH; h++) {
            float w = s_sc[h][pos];
            a[h].x += w * xv.x; a[h].y += w * xv.y;
        }
    }
    #pragma unroll
    for (int h = 0; h < HH; h++)
        *(float2*)&s_part[pg][h][ec*2] = a[h];
    __syncthreads();

    int h2 = tid >> 8, e2 = tid & 255;
    float s = 0.f;
    #pragma unroll
    for (int g = 0; g < 8; g++) s += s_part[g][h2][e2];
    g_xbar[(size_t)bc * HID + tid] = s;
}

// ====== full-reduction GEMM (mha / ffn2): CTA = 4 tok x 64 f, grid (64,4) ======
// thread: fc = tid&15 (f-quad), rg = tid>>4. Chunk = 16 j rows (4KB), 4-deep
// per-thread pipeline: each thread cp.asyncs ONLY the 16B it consumes.
#define GEMM4_BODY(WSRC, ACTSRC)                                                     \
    int t0 = blockIdx.x * 4;                                                         \
    int bf0 = blockIdx.y * 64;                                                       \
    int tid = threadIdx.x;                                                           \
    int fc = tid & 15, rg = tid >> 4;                                                \
    const float* Wb = WSRC + (size_t)rg * EE + bf0 + fc*4;                           \
    _Pragma("unroll")                                                                \
    for (int c = 0; c < 4; c++) {                                                    \
        cp_async16(&s_w[c][rg][fc*4], (const float4*)(Wb + (size_t)(c*16) * EE));    \
        cp_commit();                                                                 \
    }                                                                                \
    _Pragma("unroll")                                                                \
    for (int r = 0; r < 16; r++) {                                                   \
        int idx = r*256 + tid;                                                       \
        int t = idx >> 10, j = idx & 1023;                                           \
        s_act[j][t] = ACTSRC[(size_t)(t0 + t) * HID + j];                            \
    }                                                                                \
    float4 a[4];                                                                     \
    _Pragma("unroll")                                                                \
    for (int t = 0; t < 4; t++) a[t] = make_float4(0.f,0.f,0.f,0.f);                 \
    __syncthreads();   /* acts visible */                                            \
    _Pragma("unroll 4")                                                              \
    for (int c = 0; c < 64; c++) {                                                   \
        CPWAIT(3);                                                                   \
        float4 m  = *(const float4*)&s_w[c & 3][rg][fc*4];                           \
        float4 tv = *(const float4*)&s_act[c*16 + rg][0];                            \
        ACC4(m, tv);                                                                 \
        if (c + 4 < 64)                                                              \
            cp_async16(&s_w[c & 3][rg][fc*4], (const float4*)(Wb + (size_t)((c+4)*16) * EE)); \
        cp_commit();                                                                 \
    }                                                                                \
    __syncthreads();                                                                 \
    float* s_acc = (float*)s_w;    /* [16 rg][4 t][64 f] = 16KB overlay */           \
    _Pragma("unroll")                                                                \
    for (int t = 0; t < 4; t++)                                                      \
        *(float4*)&s_acc[(rg*4 + t)*64 + fc*4] = a[t];                               \
    __syncthreads();                                                                 \
    int ot = tid >> 6, of = tid & 63;                                                \
    float s = 0.f;                                                                   \
    _Pragma("unroll")                                                                \
    for (int g = 0; g < 16; g++) s += s_acc[(g*4 + ot)*64 + of];

__global__ __launch_bounds__(256) void mha_kernel() {
    __shared__ __align__(16) float s_act[1024][4];   // 16KB
    __shared__ __align__(16) float s_w[4][16][64];   // 16KB (overlay s_acc)
    GEMM4_BODY(g_M2T, g_xbar)
    g_mha[(size_t)(t0 + ot) * EE + bf0 + of] = s;
}

__global__ __launch_bounds__(256) void ffn2_kernel(const float* __restrict__ b2,
                                                   const int* __restrict__ real_cols,
                                                   float* __restrict__ out) {
    __shared__ __align__(16) float s_act[1024][4];
    __shared__ __align__(16) float s_w[4][16][64];
    GEMM4_BODY(g_W2T, g_hid)
    int tok = t0 + ot;
    int bidx = tok >> 5, cidx = tok & 31;
    bool valid = cidx < real_cols[bidx];
    float v = g_ln[(size_t)tok * EE + bf0 + of] + s + b2[bf0 + of];
    out[(size_t)tok * EE + bf0 + of] = valid ? v : 0.f;
}

// ---------------- kernel: FFN hidden + fused LN: CTA = 4 tok x 256 j, grid (64,4) ----------------
// thread: jq = tid&63 (j-quad), rg = tid>>6 (e mod 4). Chunk = 4 e rows (4KB), 4-deep.
__global__ __launch_bounds__(256) void ffn1_kernel(const float* __restrict__ b1,
                                                   const float* __restrict__ ln_g,
                                                   const float* __restrict__ ln_b) {
    __shared__ __align__(16) float s_lnT[EE][4];     // 4KB [e][t]
    __shared__ __align__(16) float s_w[4][4][256];   // 16KB (overlay s_acc)
    __shared__ float s_red[8][4];
    __shared__ float s_mu[4], s_rs[4];

    int t0 = blockIdx.x * 4;
    int bj0 = blockIdx.y * 256;
    int tid = threadIdx.x;
    int jq = tid & 63, rg = tid >> 6;
    int warp = tid >> 5, lane = tid & 31;

    const float* Wb = g_W1T + (size_t)rg * HID + bj0 + jq*4;
    #pragma unroll
    for (int c = 0; c < 4; c++) {
        cp_async16(&s_w[c][rg][jq*4], (const float4*)(Wb + (size_t)(c*4) * HID));
        cp_commit();
    }

    // ---- fused LN: thread tid owns e=tid for 4 tokens ----
    float v[4];
    {
        float bias = g_bias2[tid];
        #pragma unroll
        for (int t = 0; t < 4; t++)
            v[t] = g_mha[(size_t)(t0 + t) * EE + tid] + bias;
    }
    #pragma unroll
    for (int t = 0; t < 4; t++) {
        float s = v[t];
        #pragma unroll
        for (int o = 16; o; o >>= 1) s += __shfl_xor_sync(0xffffffffu, s, o);
        if (lane == 0) s_red[warp][t] = s;
    }
    __syncthreads();
    if (tid < 4) {
        float s = 0.f;
        #pragma unroll
        for (int w = 0; w < 8; w++) s += s_red[w][tid];
        s_mu[tid] = s * (1.f/EE);
    }
    __syncthreads();
    #pragma unroll
    for (int t = 0; t < 4; t++) {
        float d = v[t] - s_mu[t];
        float s = d * d;
        #pragma unroll
        for (int o = 16; o; o >>= 1) s += __shfl_xor_sync(0xffffffffu, s, o);
        if (lane == 0) s_red[warp][t] = s;
    }
    __syncthreads();
    if (tid < 4) {
        float s = 0.f;
        #pragma unroll
        for (int w = 0; w < 8; w++) s += s_red[w][tid];
        s_rs[tid] = rsqrtf(s * (1.f/EE) + LN_EPS);
    }
    __syncthreads();
    {
        float lg = ln_g[tid], lb = ln_b[tid];
        bool store_ln = (blockIdx.y == 0);
        #pragma unroll
        for (int t = 0; t < 4; t++) {
            float lnv = (v[t] - s_mu[t]) * s_rs[t] * lg + lb;
            s_lnT[tid][t] = lnv;
            if (store_ln) g_ln[(size_t)(t0 + t) * EE + tid] = lnv;
        }
    }
    float4 a[4];
    #pragma unroll
    for (int t = 0; t < 4; t++) a[t] = make_float4(0.f,0.f,0.f,0.f);
    __syncthreads();   // s_lnT visible

    #pragma unroll 4
    for (int c = 0; c < 64; c++) {
        CPWAIT(3);
        float4 m  = *(const float4*)&s_w[c & 3][rg][jq*4];
        float4 tv = *(const float4*)&s_lnT[c*4 + rg][0];
        ACC4(m, tv);
        if (c + 4 < 64)
            cp_async16(&s_w[c & 3][rg][jq*4], (const float4*)(Wb + (size_t)((c+4)*4) * HID));
        cp_commit();
    }

    __syncthreads();
    float* s_acc = (float*)s_w;    // [4 rg][4 t][256 j] overlay
    #pragma unroll
    for (int t = 0; t < 4; t++)
        *(float4*)&s_acc[(rg*4 + t)*256 + jq*4] = a[t];
    __syncthreads();

    #pragma unroll
    for (int r = 0; r < 4; r++) {
        int idx = r*256 + tid;
        int t = idx >> 8, j = idx & 255;
        float s = s_acc[(0*4 + t)*256 + j] + s_acc[(1*4 + t)*256 + j]
                + s_acc[(2*4 + t)*256 + j] + s_acc[(3*4 + t)*256 + j];
        g_hid[(size_t)(t0 + t) * HID + bj0 + j] = fmaxf(s + b1[bj0 + j], 0.f);
    }
}

// ---------------- launch ----------------
extern "C" void kernel_launch(void* const* d_in, const int* in_sizes, int n_in,
                              void* d_out, int out_size) {
    const float* x         = (const float*)d_in[0];
    const int*   real_cols = (const int*)  d_in[1];
    const int*   real_rows = (const int*)  d_in[2];
    const float* cls       = (const float*)d_in[3];
    const float* w_qkv     = (const float*)d_in[4];
    const float* b_qkv     = (const float*)d_in[5];
    const float* w_out     = (const float*)d_in[6];
    const float* b_out     = (const float*)d_in[7];
    const float* ln_g      = (const float*)d_in[8];
    const float* ln_b      = (const float*)d_in[9];
    const float* w1        = (const float*)d_in[10];
    const float* b1        = (const float*)d_in[11];
    const float* w2        = (const float*)d_in[12];
    const float* b2        = (const float*)d_in[13];
    float* out = (float*)d_out;

    // fork: setupB runs concurrently with setupA + attn
    cudaEventRecord(g_ss.fork, 0);
    cudaStreamWaitEvent(g_ss.s, g_ss.fork, 0);
    setupB_kernel<<<584, 256, 0, g_ss.s>>>(w_qkv, b_qkv, w_out, b_out, w1, w2);
    cudaEventRecord(g_ss.join, g_ss.s);

    setupA_kernel<<<9, 256>>>(cls, w_qkv, b_qkv);
    attn_kernel<<<NBC, 1024>>>(x, real_rows, cls);

    cudaStreamWaitEvent(0, g_ss.join, 0);
    mha_kernel<<<dim3(64, 4), 256>>>();
    ffn1_kernel<<<dim3(64, 4), 256>>>(b1, ln_g, ln_b);
    ffn2_kernel<<<dim3(64, 4), 256>>>(b2, real_cols, out);
}

// round 15
// speedup vs baseline: 1.2042x; 1.2042x over previous
#include <cuda_runtime.h>
#include <cuda_bf16.h>
#include <cstdint>

#define EE    256
#define HH    4
#define DH    64
#define BB    8
#define CC    32
#define RR    255
#define SS    256
#define HID   1024
#define NBC   (BB*CC)
#define TOK   8
#define LN_EPS 1e-5f

// ---------------- device scratch ----------------
__device__ __align__(16) float g_u[HH*EE];
__device__ __align__(16) float g_cb[HH];
__device__ __align__(16) float g_bias2[EE];
__device__ __align__(16) float g_M2T[HID*EE];      // [j][f]
__device__ __align__(16) float g_W1T[EE*HID];      // [e][j]
__device__ __align__(16) float g_W2T[HID*EE];      // [j][f]
__device__ __align__(16) float g_xbar[NBC*HID];
__device__ __align__(16) float g_mha[NBC*EE];
__device__ __align__(16) float g_ln[NBC*EE];
__device__ __align__(16) float g_hid[NBC*HID];

// ---------------- cp.async helpers ----------------
__device__ __forceinline__ void cp_async16(float* sdst, const float4* gsrc) {
    unsigned sa = (unsigned)__cvta_generic_to_shared(sdst);
    asm volatile("cp.async.ca.shared.global [%0], [%1], 16;" :: "r"(sa), "l"(gsrc));
}
__device__ __forceinline__ void cp_commit() { asm volatile("cp.async.commit_group;"); }
#define CPWAIT(n) asm volatile("cp.async.wait_group " #n ";")

// 8-token FMA: a[t] (float4 over the thread's 4 outputs) += m * act[t]
#define ACC8(m, tA, tB) do { \
    a[0].x += (m).x*(tA).x; a[0].y += (m).y*(tA).x; a[0].z += (m).z*(tA).x; a[0].w += (m).w*(tA).x; \
    a[1].x += (m).x*(tA).y; a[1].y += (m).y*(tA).y; a[1].z += (m).z*(tA).y; a[1].w += (m).w*(tA).y; \
    a[2].x += (m).x*(tA).z; a[2].y += (m).y*(tA).z; a[2].z += (m).z*(tA).z; a[2].w += (m).w*(tA).z; \
    a[3].x += (m).x*(tA).w; a[3].y += (m).y*(tA).w; a[3].z += (m).z*(tA).w; a[3].w += (m).w*(tA).w; \
    a[4].x += (m).x*(tB).x; a[4].y += (m).y*(tB).x; a[4].z += (m).z*(tB).x; a[4].w += (m).w*(tB).x; \
    a[5].x += (m).x*(tB).y; a[5].y += (m).y*(tB).y; a[5].z += (m).z*(tB).y; a[5].w += (m).w*(tB).y; \
    a[6].x += (m).x*(tB).z; a[6].y += (m).y*(tB).z; a[6].z += (m).z*(tB).z; a[6].w += (m).w*(tB).z; \
    a[7].x += (m).x*(tB).w; a[7].y += (m).y*(tB).w; a[7].z += (m).z*(tB).w; a[7].w += (m).w*(tB).w; \
} while(0)

__device__ __forceinline__ float warp_dot256(const float* __restrict__ row,
                                             const float* __restrict__ svec, int lane) {
    float4 w0 = *(const float4*)(row + lane*4);
    float4 w1 = *(const float4*)(row + 128 + lane*4);
    float4 c0 = *(const float4*)(svec + lane*4);
    float4 c1 = *(const float4*)(svec + 128 + lane*4);
    float acc = w0.x*c0.x + w0.y*c0.y + w0.z*c0.z + w0.w*c0.w
              + w1.x*c1.x + w1.y*c1.y + w1.z*c1.z + w1.w*c1.w;
    #pragma unroll
    for (int o = 16; o; o >>= 1) acc += __shfl_xor_sync(0xffffffffu, acc, o);
    return acc;
}

// ---------------- kernel: setup (verified R9-R12) ----------------
// [0,64): M2T | [64,576): transposes | [576,584): u (local q0) | 584: cb | [585,593): bias2
__global__ __launch_bounds__(256) void setup_kernel(const float* __restrict__ cls,
                              const float* __restrict__ w_qkv,
                              const float* __restrict__ b_qkv,
                              const float* __restrict__ w_out,
                              const float* __restrict__ b_out,
                              const float* __restrict__ w1,
                              const float* __restrict__ w2) {
    int bi = blockIdx.x;
    int tid = threadIdx.x;

    if (bi < 64) {
        __shared__ float sa[64][64];
        __shared__ float sb[64][65];
        int h = bi >> 4, e0 = ((bi >> 2) & 3) * 64, f0 = (bi & 3) * 64;
        for (int i = tid; i < 4096; i += 256) {
            int d = i >> 6, el = i & 63;
            sa[d][el] = w_qkv[(size_t)(2*EE + h*64 + d) * EE + e0 + el];
        }
        for (int i = tid; i < 4096; i += 256) {
            int fl = i >> 6, d = i & 63;
            sb[fl][d] = w_out[(size_t)(f0 + fl) * EE + h*64 + d];
        }
        __syncthreads();
        int tx = tid & 15, ty = tid >> 4;
        float acc[4][4] = {};
        #pragma unroll 4
        for (int d = 0; d < 64; d++) {
            float av[4], bv[4];
            #pragma unroll
            for (int i = 0; i < 4; i++) av[i] = sa[d][ty*4 + i];
            #pragma unroll
            for (int i = 0; i < 4; i++) bv[i] = sb[tx*4 + i][d];
            #pragma unroll
            for (int i = 0; i < 4; i++)
                #pragma unroll
                for (int j = 0; j < 4; j++) acc[i][j] += av[i] * bv[j];
        }
        #pragma unroll
        for (int i = 0; i < 4; i++)
            *(float4*)&g_M2T[(size_t)(h*256 + e0 + ty*4 + i) * EE + f0 + tx*4] = *(float4*)acc[i];
        return;
    }
    if (bi < 576) {
        __shared__ float s[32][33];
        int a = bi - 64;
        const float* src; float* dst; int rows, cols, bx, by;
        if (a < 256) {
            src = w1; dst = g_W1T; rows = HID; cols = EE;
            bx = (a & 7) * 32; by = (a >> 3) * 32;
        } else {
            a -= 256;
            src = w2; dst = g_W2T; rows = EE; cols = HID;
            bx = (a & 31) * 32; by = (a >> 5) * 32;
        }
        int tx = tid & 31, ty = tid >> 5;
        #pragma unroll
        for (int r = 0; r < 4; r++)
            s[ty + r*8][tx] = src[(size_t)(by + ty + r*8) * cols + bx + tx];
        __syncthreads();
        #pragma unroll
        for (int r = 0; r < 4; r++)
            dst[(size_t)(bx + ty + r*8) * rows + by + tx] = s[tx][ty + r*8];
        return;
    }
    if (bi < 584) {
        __shared__ float s_cls[EE];
        __shared__ float s_q[DH];
        __shared__ float s_p[2][128];
        int k = bi - 576;
        int h = k >> 1, e0 = (k & 1) * 128;
        int warp = tid >> 5, lane = tid & 31;
        if (tid < EE) s_cls[tid] = cls[tid];
        __syncthreads();
        #pragma unroll
        for (int r = 0; r < 8; r++) {
            int d = warp*8 + r;
            float acc = warp_dot256(w_qkv + (size_t)(h*DH + d) * EE, s_cls, lane);
            if (lane == 0) s_q[d] = acc + b_qkv[h*DH + d];
        }
        __syncthreads();
        int dg = tid >> 7, e = e0 + (tid & 127);
        float acc = 0.f;
        #pragma unroll 8
        for (int i = 0; i < 32; i++) {
            int d = dg*32 + i;
            acc += s_q[d] * w_qkv[(size_t)(EE + h*DH + d) * EE + e];
        }
        s_p[dg][tid & 127] = acc;
        __syncthreads();
        if (tid < 128)
            g_u[h*EE + e0 + tid] = 0.125f * (s_p[0][tid] + s_p[1][tid]);
        return;
    }
    if (bi == 584) {
        __shared__ float s_cls[EE];
        __shared__ float s_q0[EE];
        __shared__ float s_w[8];
        int warp = tid >> 5, lane = tid & 31;
        if (tid < EE) s_cls[tid] = cls[tid];
        __syncthreads();
        for (int r = 0; r < 32; r++) {
            int row = warp*32 + r;
            float acc = warp_dot256(w_qkv + (size_t)row * EE, s_cls, lane);
            if (lane == 0) s_q0[row] = acc + b_qkv[row];
        }
        __syncthreads();
        float v = s_q0[tid] * b_qkv[EE + tid];
        #pragma unroll
        for (int o = 16; o; o >>= 1) v += __shfl_xor_sync(0xffffffffu, v, o);
        if ((tid & 31) == 0) s_w[tid >> 5] = v;
        __syncthreads();
        if (tid < HH) g_cb[tid] = 0.125f * (s_w[2*tid] + s_w[2*tid + 1]);
        return;
    }
    {
        __shared__ float s_bv[EE];
        int base = (bi - 585) * 32;
        int warp = tid >> 5, lane = tid & 31;
        if (tid < EE) s_bv[tid] = b_qkv[2*EE + tid];
        __syncthreads();
        #pragma unroll
        for (int q = 0; q < 4; q++) {
            int f = base + warp * 4 + q;
            float acc = warp_dot256(w_out + (size_t)f * EE, s_bv, lane);
            if (lane == 0) g_bias2[f] = acc + b_out[f];
        }
    }
}

// ---------------- kernel: attention -> xbar (verified R7-R12) ----------------
__global__ __launch_bounds__(1024) void attn_kernel(const float* __restrict__ x,
                            const int* __restrict__ real_rows,
                            const float* __restrict__ cls) {
    __shared__ __align__(16) float s_u[HH*EE];
    __shared__ __align__(16) float s_sc[HH][SS];
    __shared__ __align__(16) float s_cls[EE];
    __shared__ __align__(16) float s_part[8][HH][EE];
    __shared__ float s_cb[HH];

    int bc  = blockIdx.x;
    int b   = bc >> 5;
    int tid = threadIdx.x;
    int warp = tid >> 5, lane = tid & 31;

    s_u[tid] = g_u[tid];
    if (tid < EE) s_cls[tid] = cls[tid];
    if (tid < HH) s_cb[tid] = g_cb[tid];
    __syncthreads();

    int nk = real_rows[b] + 1;
    const float* xbase = x + (size_t)bc * RR * EE;

    {
        int pos = warp;
        bool have = pos < nk;
        float4 v0, v1;
        if (have) {
            const float* row = (pos == 0) ? s_cls : (xbase + (size_t)(pos - 1) * EE);
            v0 = *(const float4*)(row + lane*4);
            v1 = *(const float4*)(row + 128 + lane*4);
        }
        while (have) {
            int npos = pos + 32;
            bool nh = npos < nk;
            float4 n0, n1;
            if (nh) {
                const float* nrow = xbase + (size_t)(npos - 1) * EE;
                n0 = *(const float4*)(nrow + lane*4);
                n1 = *(const float4*)(nrow + 128 + lane*4);
            }
            float acc[HH];
            #pragma unroll
            for (int h = 0; h < HH; h++) {
                float4 u0 = *(const float4*)(s_u + h*EE + lane*4);
                float4 u1 = *(const float4*)(s_u + h*EE + 128 + lane*4);
                acc[h] = v0.x*u0.x + v0.y*u0.y + v0.z*u0.z + v0.w*u0.w
                       + v1.x*u1.x + v1.y*u1.y + v1.z*u1.z + v1.w*u1.w;
            }
            #pragma unroll
            for (int o = 16; o; o >>= 1) {
                #pragma unroll
                for (int h = 0; h < HH; h++)
                    acc[h] += __shfl_xor_sync(0xffffffffu, acc[h], o);
            }
            if (lane == 0) {
                #pragma unroll
                for (int h = 0; h < HH; h++) s_sc[h][pos] = acc[h] + s_cb[h];
            }
            pos = npos; have = nh; v0 = n0; v1 = n1;
        }
    }
    __syncthreads();

    if (warp < HH) {
        int h = warp;
        float m = -3.0e38f;
        for (int p = lane; p < nk; p += 32) m = fmaxf(m, s_sc[h][p]);
        #pragma unroll
        for (int o = 16; o; o >>= 1) m = fmaxf(m, __shfl_xor_sync(0xffffffffu, m, o));
        float sum = 0.f;
        for (int p = lane; p < nk; p += 32) {
            float ev = __expf(s_sc[h][p] - m);
            s_sc[h][p] = ev;
            sum += ev;
        }
        #pragma unroll
        for (int o = 16; o; o >>= 1) sum += __shfl_xor_sync(0xffffffffu, sum, o);
        float inv = 1.f / sum;
        for (int p = lane; p < nk; p += 32) s_sc[h][p] *= inv;
    }
    __syncthreads();

    int pg = tid >> 7, ec = tid & 127;
    float2 a[HH];
    #pragma unroll
    for (int h = 0; h < HH; h++) a[h] = make_float2(0.f, 0.f);
    #pragma unroll 8
    for (int pos = pg; pos < nk; pos += 8) {
        float2 xv = (pos == 0) ? *(const float2*)(s_cls + ec*2)
                               : *(const float2*)(xbase + (size_t)(pos - 1) * EE + ec*2);
        #pragma unroll
        for (int h = 0; h < HH; h++) {
            float w = s_sc[h][pos];
            a[h].x += w * xv.x; a[h].y += w * xv.y;
        }
    }
    #pragma unroll
    for (int h = 0; h < HH; h++)
        *(float2*)&s_part[pg][h][ec*2] = a[h];
    __syncthreads();

    int h2 = tid >> 8, e2 = tid & 255;
    float s = 0.f;
    #pragma unroll
    for (int g = 0; g < 8; g++) s += s_part[g][h2][e2];
    g_xbar[(size_t)bc * HID + tid] = s;
}

// ====== GEMM (mha / ffn2): CTA = 8 tok x 32 f, full K=1024, grid (32,8) ======
// thread: fq = tid&7 (f-quad), rg = tid>>3 (j mod-32 class). Per chunk of 32 j:
// thread's j = c*32+rg; 1 weight LDS.128 + 2 broadcast act LDS.128 + 32 FFMA.
// Weights stream thread-private 16B cp.async, 4-deep; NO mainloop syncs.
#define GEMMA_BODY(WSRC, ACTSRC)                                                     \
    int t0 = blockIdx.x * TOK;                                                       \
    int f0 = blockIdx.y * 32;                                                        \
    int tid = threadIdx.x;                                                           \
    int fq = tid & 7, rg = tid >> 3;                                                 \
    const float* Wb = WSRC + (size_t)rg * EE + f0 + fq*4;                            \
    _Pragma("unroll")                                                                \
    for (int c = 0; c < 4; c++) {                                                    \
        cp_async16(&s_w[c][rg][fq*4], (const float4*)(Wb + (size_t)(c*32) * EE));    \
        cp_commit();                                                                 \
    }                                                                                \
    _Pragma("unroll")                                                                \
    for (int r = 0; r < 32; r++) {                                                   \
        int idx = r*256 + tid;                                                       \
        int t = idx >> 10, j = idx & 1023;                                           \
        s_act[j][t] = ACTSRC[(size_t)(t0 + t) * HID + j];                            \
    }                                                                                \
    float4 a[TOK];                                                                   \
    _Pragma("unroll")                                                                \
    for (int t = 0; t < TOK; t++) a[t] = make_float4(0.f,0.f,0.f,0.f);               \
    __syncthreads();   /* acts visible to all */                                     \
    _Pragma("unroll 4")                                                              \
    for (int c = 0; c < 32; c++) {                                                   \
        CPWAIT(3);                                                                   \
        float4 m  = *(const float4*)&s_w[c & 3][rg][fq*4];                           \
        float4 tA = *(const float4*)&s_act[c*32 + rg][0];                            \
        float4 tB = *(const float4*)&s_act[c*32 + rg][4];                            \
        ACC8(m, tA, tB);                                                             \
        if (c + 4 < 32)                                                              \
            cp_async16(&s_w[c & 3][rg][fq*4], (const float4*)(Wb + (size_t)((c+4)*32) * EE)); \
        cp_commit();                                                                 \
    }                                                                                \
    __syncthreads();                                                                 \
    float* s_acc = (float*)s_act;    /* [32 rg][8 t][32 f] = 32KB overlay */         \
    _Pragma("unroll")                                                                \
    for (int t = 0; t < TOK; t++)                                                    \
        *(float4*)&s_acc[(rg*TOK + t)*32 + fq*4] = a[t];                             \
    __syncthreads();                                                                 \
    int ot = tid >> 5, of = tid & 31;                                                \
    float s = 0.f;                                                                   \
    _Pragma("unroll")                                                                \
    for (int g = 0; g < 32; g++) s += s_acc[(g*TOK + ot)*32 + of];

__global__ __launch_bounds__(256) void mha_kernel() {
    __shared__ __align__(16) float s_act[1024][TOK];   // 32KB (overlay s_acc)
    __shared__ __align__(16) float s_w[4][32][32];     // 16KB
    GEMMA_BODY(g_M2T, g_xbar)
    g_mha[(size_t)(t0 + ot) * EE + f0 + of] = s;
}

__global__ __launch_bounds__(256) void ffn2_kernel(const float* __restrict__ b2,
                                                   const int* __restrict__ real_cols,
                                                   float* __restrict__ out) {
    __shared__ __align__(16) float s_act[1024][TOK];
    __shared__ __align__(16) float s_w[4][32][32];
    GEMMA_BODY(g_W2T, g_hid)
    int tok = t0 + ot;
    int bidx = tok >> 5, cidx = tok & 31;
    bool valid = cidx < real_cols[bidx];
    float v = g_ln[(size_t)tok * EE + f0 + of] + s + b2[f0 + of];
    out[(size_t)tok * EE + f0 + of] = valid ? v : 0.f;
}

// ---------------- kernel: FFN hidden: CTA = 8 tok x 128 j, full K=256, grid (32,8) ----------------
// thread: jq = tid&31 (j-quad), rg = tid>>5 (e mod-8 class). Chunk = 8 e rows.
__global__ __launch_bounds__(256) void ffn1_kernel(const float* __restrict__ b1) {
    __shared__ __align__(16) float s_lnT[EE][TOK];     // 8KB [e][t]
    __shared__ __align__(16) float s_un[8192];          // 32KB: s_w[4][8][128] (16KB) | s_acc[8][8][128]
    float (*s_w)[8][128] = (float(*)[8][128])s_un;

    int t0 = blockIdx.x * TOK;
    int j0 = blockIdx.y * 128;
    int tid = threadIdx.x;
    int jq = tid & 31, rg = tid >> 5;

    const float* Wb = g_W1T + (size_t)rg * HID + j0 + jq*4;
    #pragma unroll
    for (int c = 0; c < 4; c++) {
        cp_async16(&s_w[c][rg][jq*4], (const float4*)(Wb + (size_t)(c*8) * HID));
        cp_commit();
    }
    #pragma unroll
    for (int r = 0; r < 8; r++) {
        int idx = r*256 + tid;
        int t = idx >> 8, e = idx & 255;
        s_lnT[e][t] = g_ln[(size_t)(t0 + t) * EE + e];
    }
    float4 a[TOK];
    #pragma unroll
    for (int t = 0; t < TOK; t++) a[t] = make_float4(0.f,0.f,0.f,0.f);
    __syncthreads();

    #pragma unroll 4
    for (int c = 0; c < 32; c++) {
        CPWAIT(3);
        float4 m  = *(const float4*)&s_w[c & 3][rg][jq*4];
        float4 tA = *(const float4*)&s_lnT[c*8 + rg][0];
        float4 tB = *(const float4*)&s_lnT[c*8 + rg][4];
        ACC8(m, tA, tB);
        if (c + 4 < 32)
            cp_async16(&s_w[c & 3][rg][jq*4], (const float4*)(Wb + (size_t)((c+4)*8) * HID));
        cp_commit();
    }

    __syncthreads();
    float* s_acc = s_un;    // [8 rg][8 t][128 j] = 32KB
    #pragma unroll
    for (int t = 0; t < TOK; t++)
        *(float4*)&s_acc[(rg*TOK + t)*128 + jq*4] = a[t];
    __syncthreads();

    #pragma unroll
    for (int r = 0; r < 4; r++) {
        int idx = r*256 + tid;
        int t = idx >> 7, j = idx & 127;
        float s = 0.f;
        #pragma unroll
        for (int g = 0; g < 8; g++) s += s_acc[(g*TOK + t)*128 + j];
        g_hid[(size_t)(t0 + t) * HID + j0 + j] = fmaxf(s + b1[j0 + j], 0.f);
    }
}

// ---------------- kernel: LayerNorm (block per token; verified R11) ----------------
__device__ __forceinline__ float blk_sum256(float v, volatile float* s8, int tid) {
    #pragma unroll
    for (int o = 16; o; o >>= 1) v += __shfl_xor_sync(0xffffffffu, v, o);
    if ((tid & 31) == 0) s8[tid >> 5] = v;
    __syncthreads();
    float r = s8[0]+s8[1]+s8[2]+s8[3]+s8[4]+s8[5]+s8[6]+s8[7];
    __syncthreads();
    return r;
}

__global__ __launch_bounds__(256) void lnred_kernel(const float* __restrict__ ln_g,
                             const float* __restrict__ ln_b) {
    __shared__ float s8[8];
    int t = blockIdx.x;
    int tid = threadIdx.x;
    float v = g_mha[(size_t)t * EE + tid] + g_bias2[tid];
    float mu = blk_sum256(v, s8, tid) * (1.f/EE);
    float d = v - mu;
    float var = blk_sum256(d*d, s8, tid) * (1.f/EE);
    g_ln[(size_t)t * EE + tid] = d * rsqrtf(var + LN_EPS) * ln_g[tid] + ln_b[tid];
}

// ---------------- launch ----------------
extern "C" void kernel_launch(void* const* d_in, const int* in_sizes, int n_in,
                              void* d_out, int out_size) {
    const float* x         = (const float*)d_in[0];
    const int*   real_cols = (const int*)  d_in[1];
    const int*   real_rows = (const int*)  d_in[2];
    const float* cls       = (const float*)d_in[3];
    const float* w_qkv     = (const float*)d_in[4];
    const float* b_qkv     = (const float*)d_in[5];
    const float* w_out     = (const float*)d_in[6];
    const float* b_out     = (const float*)d_in[7];
    const float* ln_g      = (const float*)d_in[8];
    const float* ln_b      = (const float*)d_in[9];
    const float* w1        = (const float*)d_in[10];
    const float* b1        = (const float*)d_in[11];
    const float* w2        = (const float*)d_in[12];
    const float* b2        = (const float*)d_in[13];
    float* out = (float*)d_out;

    setup_kernel<<<593, 256>>>(cls, w_qkv, b_qkv, w_out, b_out, w1, w2);
    attn_kernel<<<NBC, 1024>>>(x, real_rows, cls);
    mha_kernel<<<dim3(NBC/TOK, 8), 256>>>();
    lnred_kernel<<<NBC, 256>>>(ln_g, ln_b);
    ffn1_kernel<<<dim3(NBC/TOK, 8), 256>>>(b1);
    ffn2_kernel<<<dim3(NBC/TOK, 8), 256>>>(b2, real_cols, out);
}